// round 3
// baseline (speedup 1.0000x reference)
#include <cuda_runtime.h>
#include <math.h>

#define B_ 128
#define L_ 128
#define T_ (B_*L_)
#define DIN_ 6
#define D_ 256
#define H_ 8
#define DK_ 32
#define NL_ 6
#define NE_ 8
#define DFF_ 1024
#define NOUT_ 5

#define ATTN_SMEM ((128*33 + 128*129 + 128)*4)
#define FFN_SMEM  ((32*257 + 8192 + 32*33)*4)

// ---------------- device scratch (no allocations allowed) ----------------
__device__ float g_h[T_*D_];
__device__ float g_q[T_*D_];
__device__ float g_k[T_*D_];
__device__ float g_v[T_*D_];
__device__ float g_ao[T_*D_];
__device__ float g_eo[(size_t)NE_*T_*D_];   // per-expert FFN outputs by list position
__device__ int   g_cnt[NE_];
__device__ int   g_list[NE_*T_];
__device__ int   g_ebuf[T_*2];
__device__ int   g_pbuf[T_*2];
__device__ float g_wbuf[T_*2];

// ---------------- embed: h = x @ emb_w + emb_b ----------------
__global__ void embed_kernel(const float* __restrict__ x,
                             const float* __restrict__ w,
                             const float* __restrict__ b) {
    int t = blockIdx.x, d = threadIdx.x;
    float acc = b[d];
#pragma unroll
    for (int i = 0; i < DIN_; i++) acc += x[t*DIN_ + i] * w[i*D_ + d];
    g_h[(size_t)t*D_ + d] = acc;
}

// ---------------- SGEMM: C[M,256] = A[M,256] @ W[256,256] (+res) ----------------
// BM=128, BN=64, BK=16, 256 threads, 8x4 microtile
__global__ void sgemm128(const float* __restrict__ A, const float* __restrict__ W,
                         const float* res, float* C) {
    __shared__ float As[16][132];   // padded (x4) to reduce STS conflicts, keep f4 align
    __shared__ float Bs[16][64];
    int brow = blockIdx.y * 128, bcol = blockIdx.x * 64;
    int tid = threadIdx.x;
    int trow = (tid >> 4) << 3;     // (tid/16)*8
    int tcol = (tid & 15) << 2;     // (tid%16)*4
    float acc[8][4];
#pragma unroll
    for (int m = 0; m < 8; m++)
#pragma unroll
        for (int n = 0; n < 4; n++) acc[m][n] = 0.f;

    for (int k0 = 0; k0 < D_; k0 += 16) {
#pragma unroll
        for (int i = tid; i < 128*16; i += 256) {
            int r = i >> 4, c = i & 15;
            As[c][r] = A[(size_t)(brow + r)*D_ + k0 + c];
        }
#pragma unroll
        for (int i = tid; i < 16*64; i += 256) {
            int r = i >> 6, c = i & 63;
            Bs[r][c] = W[(size_t)(k0 + r)*D_ + bcol + c];
        }
        __syncthreads();
#pragma unroll
        for (int kk = 0; kk < 16; kk++) {
            float4 a0 = *(const float4*)&As[kk][trow];
            float4 a1 = *(const float4*)&As[kk][trow + 4];
            float4 bb = *(const float4*)&Bs[kk][tcol];
            float av[8] = {a0.x,a0.y,a0.z,a0.w,a1.x,a1.y,a1.z,a1.w};
            float bv[4] = {bb.x,bb.y,bb.z,bb.w};
#pragma unroll
            for (int m = 0; m < 8; m++)
#pragma unroll
                for (int n = 0; n < 4; n++) acc[m][n] += av[m]*bv[n];
        }
        __syncthreads();
    }
#pragma unroll
    for (int m = 0; m < 8; m++) {
        size_t idx = (size_t)(brow + trow + m)*D_ + bcol + tcol;
        float4 v = make_float4(acc[m][0], acc[m][1], acc[m][2], acc[m][3]);
        if (res) {
            float4 r4 = *(const float4*)(res + idx);
            v.x += r4.x; v.y += r4.y; v.z += r4.z; v.w += r4.w;
        }
        *(float4*)(C + idx) = v;
    }
}

// ---------------- wave attention: one block per (b, head) ----------------
__global__ void attn_kernel(const float* __restrict__ q, const float* __restrict__ k,
                            const float* __restrict__ v, const float* __restrict__ wfreq,
                            const float* __restrict__ wphase, float* __restrict__ out,
                            int layer) {
    extern __shared__ float sm[];
    float* kv  = sm;                         // 128*33 (K tile, later reused as V tile)
    float* ps  = sm + 128*33;                // 128*129 score rows (padded)
    float* wav = sm + 128*33 + 128*129;      // 128 wave values

    int b = blockIdx.x >> 3, hh = blockIdx.x & 7;
    int t = threadIdx.x;
    float freq  = wfreq[layer*H_ + hh];
    float phase = wphase[layer*H_ + hh];
    wav[t] = cosf(6.283185307179586f * freq * (float)t + phase);

    const float* qb = q + (size_t)(b*L_)*D_ + hh*DK_;
    const float* kb = k + (size_t)(b*L_)*D_ + hh*DK_;
    const float* vb = v + (size_t)(b*L_)*D_ + hh*DK_;

    for (int i = t; i < L_*DK_; i += L_) {
        int r = i >> 5, c = i & 31;
        kv[r*33 + c] = kb[(size_t)r*D_ + c];
    }
    float qr[DK_];
#pragma unroll
    for (int d = 0; d < DK_; d++) qr[d] = qb[(size_t)t*D_ + d];
    __syncthreads();

    const float scale = 0.17677669529663688f;   // 32^-0.5
    float mx = -1e30f;
    for (int j = 0; j < L_; j++) {
        float s = 0.f;
#pragma unroll
        for (int d = 0; d < DK_; d++) s += qr[d]*kv[j*33 + d];
        s = s * scale * wav[j];
        ps[t*129 + j] = s;
        mx = fmaxf(mx, s);
    }
    float sum = 0.f;
    for (int j = 0; j < L_; j++) {
        float e = expf(ps[t*129 + j] - mx);
        ps[t*129 + j] = e;
        sum += e;
    }
    float inv = 1.f / sum;
    __syncthreads();   // everyone done with K tile
    for (int i = t; i < L_*DK_; i += L_) {
        int r = i >> 5, c = i & 31;
        kv[r*33 + c] = vb[(size_t)r*D_ + c];
    }
    __syncthreads();

    float o[DK_];
#pragma unroll
    for (int d = 0; d < DK_; d++) o[d] = 0.f;
    for (int j = 0; j < L_; j++) {
        float p = ps[t*129 + j];
#pragma unroll
        for (int d = 0; d < DK_; d++) o[d] += p*kv[j*33 + d];
    }
    float* ob = out + (size_t)(b*L_ + t)*D_ + hh*DK_;
#pragma unroll
    for (int d = 0; d < DK_; d++) ob[d] = o[d]*inv;
}

// ---------------- MoE router + bucketing (one warp per token) ----------------
__global__ void reset_kernel() {
    if (threadIdx.x < NE_) g_cnt[threadIdx.x] = 0;
}

__global__ void router_kernel(const float* __restrict__ rtw, const float* __restrict__ rtb) {
    int lane = threadIdx.x & 31;
    int t = blockIdx.x*8 + (threadIdx.x >> 5);
    const float* xr = g_h + (size_t)t*D_;
    float acc[NE_];
#pragma unroll
    for (int e = 0; e < NE_; e++) acc[e] = 0.f;
    for (int d = lane; d < D_; d += 32) {
        float xv = xr[d];
#pragma unroll
        for (int e = 0; e < NE_; e++) acc[e] += xv * rtw[d*NE_ + e];
    }
#pragma unroll
    for (int off = 16; off > 0; off >>= 1)
#pragma unroll
        for (int e = 0; e < NE_; e++) acc[e] += __shfl_down_sync(0xffffffffu, acc[e], off);
    if (lane == 0) {
        float l0 = -1e30f, l1 = -1e30f; int e0 = 0, e1 = 0;
#pragma unroll
        for (int e = 0; e < NE_; e++) {
            float vv = acc[e] + rtb[e];
            if (vv > l0) { l1 = l0; e1 = e0; l0 = vv; e0 = e; }
            else if (vv > l1) { l1 = vv; e1 = e; }
        }
        float ew = expf(l1 - l0);          // normalized top-2 softmax weights
        float w0 = 1.f/(1.f + ew);
        float w1 = ew/(1.f + ew);
        int p0 = atomicAdd(&g_cnt[e0], 1); g_list[e0*T_ + p0] = t;
        int p1 = atomicAdd(&g_cnt[e1], 1); g_list[e1*T_ + p1] = t;
        g_ebuf[2*t]   = e0; g_pbuf[2*t]   = p0; g_wbuf[2*t]   = w0;
        g_ebuf[2*t+1] = e1; g_pbuf[2*t+1] = p1; g_wbuf[2*t+1] = w1;
    }
}

// ---------------- fused expert FFN: gelu(x@w1+b1)@w2+b2, 32 tokens/block ----------------
__global__ void ffn_kernel(const float* __restrict__ w1, const float* __restrict__ b1,
                           const float* __restrict__ w2, const float* __restrict__ b2) {
    int e = blockIdx.y;
    int cnt = g_cnt[e];
    int start = blockIdx.x * 32;
    if (start >= cnt) return;
    int n = cnt - start; if (n > 32) n = 32;

    extern __shared__ float sm[];
    float* xs = sm;                  // [32][257]
    float* ws = sm + 32*257;         // 8192 floats: w1 chunk [256][32] / w2 chunk [32][256]
    float* hs = ws + 8192;           // [32][33]

    int tid = threadIdx.x;
    const float* w1e = w1 + (size_t)e*D_*DFF_;
    const float* w2e = w2 + (size_t)e*DFF_*D_;
    const float* b1e = b1 + e*DFF_;
    const float* b2e = b2 + e*D_;

    for (int r = 0; r < 32; r++) {
        int tok = (r < n) ? g_list[e*T_ + start + r] : -1;
        xs[r*257 + tid] = (tok >= 0) ? g_h[(size_t)tok*D_ + tid] : 0.f;
    }

    int tokA = tid >> 3, f4 = (tid & 7) << 2;   // phase A: (token, 4 ff cols)
    int tokB = tid >> 3, dset = tid & 7;        // phase B: (token, interleaved d)
    float oacc[32];
#pragma unroll
    for (int j = 0; j < 32; j++) oacc[j] = 0.f;

    for (int c0 = 0; c0 < DFF_; c0 += 32) {
        __syncthreads();   // prior phase-B readers of ws done; xs visible on first iter
#pragma unroll
        for (int kk = 0; kk < 32; kk++) {       // w1 chunk: ws[d*32 + f]
            int i = tid + kk*256;
            ws[i] = w1e[(size_t)(i >> 5)*DFF_ + c0 + (i & 31)];
        }
        __syncthreads();
        float ha0 = 0.f, ha1 = 0.f, ha2 = 0.f, ha3 = 0.f;
#pragma unroll 4
        for (int d = 0; d < D_; d++) {
            float xv = xs[tokA*257 + d];
            float4 w4 = *(const float4*)(ws + (d << 5) + f4);
            ha0 += xv*w4.x; ha1 += xv*w4.y; ha2 += xv*w4.z; ha3 += xv*w4.w;
        }
        {
            float hb[4] = {ha0 + b1e[c0+f4], ha1 + b1e[c0+f4+1],
                           ha2 + b1e[c0+f4+2], ha3 + b1e[c0+f4+3]};
#pragma unroll
            for (int ii = 0; ii < 4; ii++) {
                float xg = hb[ii];   // exact gelu
                hs[tokA*33 + f4 + ii] = 0.5f*xg*(1.f + erff(xg*0.7071067811865475f));
            }
        }
        __syncthreads();
#pragma unroll
        for (int kk = 0; kk < 32; kk++) {       // w2 chunk: ws[f*256 + d]
            int i = tid + kk*256;
            ws[i] = w2e[(size_t)(c0 + (i >> 8))*D_ + (i & 255)];
        }
        __syncthreads();
#pragma unroll 4
        for (int f = 0; f < 32; f++) {
            float hv = hs[tokB*33 + f];
            const float4* wr = (const float4*)(ws + (f << 8));
#pragma unroll
            for (int j4 = 0; j4 < 8; j4++) {
                float4 w4 = wr[dset + (j4 << 3)];
                oacc[j4*4+0] += hv*w4.x; oacc[j4*4+1] += hv*w4.y;
                oacc[j4*4+2] += hv*w4.z; oacc[j4*4+3] += hv*w4.w;
            }
        }
    }

    if (tokB < n) {
        size_t row = (size_t)e*T_ + start + tokB;
#pragma unroll
        for (int j4 = 0; j4 < 8; j4++)
#pragma unroll
            for (int c = 0; c < 4; c++) {
                int d = (dset << 2) + (j4 << 5) + c;
                g_eo[row*D_ + d] = oacc[j4*4+c] + b2e[d];
            }
    }
}

// ---------------- combine: h += w0*eo[e0,p0] + w1*eo[e1,p1] ----------------
__global__ void combine_kernel() {
    int t = blockIdx.x, d = threadIdx.x;
    float v = g_h[(size_t)t*D_ + d];
#pragma unroll
    for (int kk = 0; kk < 2; kk++) {
        int e = g_ebuf[2*t + kk];
        int p = g_pbuf[2*t + kk];
        float w = g_wbuf[2*t + kk];
        v += w * g_eo[((size_t)e*T_ + p)*D_ + d];
    }
    g_h[(size_t)t*D_ + d] = v;
}

// ---------------- head: LN(last token) -> pred / softplus(unc) ----------------
__global__ void head_kernel(const float* __restrict__ ln_g, const float* __restrict__ ln_b,
                            const float* __restrict__ pw, const float* __restrict__ pb,
                            const float* __restrict__ uw, const float* __restrict__ ub,
                            float* __restrict__ out) {
    __shared__ float red[256];
    __shared__ float norm[256];
    int b = blockIdx.x, d = threadIdx.x;
    float hv = g_h[(size_t)(b*L_ + L_ - 1)*D_ + d];
    red[d] = hv; __syncthreads();
    for (int s = 128; s > 0; s >>= 1) { if (d < s) red[d] += red[d+s]; __syncthreads(); }
    float mu = red[0] * (1.f/256.f);
    __syncthreads();
    float df = hv - mu;
    red[d] = df*df; __syncthreads();
    for (int s = 128; s > 0; s >>= 1) { if (d < s) red[d] += red[d+s]; __syncthreads(); }
    float var = red[0] * (1.f/256.f);
    norm[d] = df * rsqrtf(var + 1e-5f) * ln_g[d] + ln_b[d];
    __syncthreads();
    if (d < 2*NOUT_) {
        int o = d % NOUT_;
        bool un = (d >= NOUT_);
        const float* W = un ? uw : pw;
        float acc = un ? ub[o] : pb[o];
        for (int i = 0; i < D_; i++) acc += norm[i]*W[i*NOUT_ + o];
        if (!un) out[b*NOUT_ + o] = acc;
        else     out[B_*NOUT_ + b*NOUT_ + o] = (acc > 20.f) ? acc : log1pf(expf(acc));
    }
}

// ---------------- launch ----------------
extern "C" void kernel_launch(void* const* d_in, const int* in_sizes, int n_in,
                              void* d_out, int out_size) {
    const float* x     = (const float*)d_in[0];
    const float* emb_w = (const float*)d_in[1];
    const float* emb_b = (const float*)d_in[2];
    const float* wq    = (const float*)d_in[3];
    const float* wk    = (const float*)d_in[4];
    const float* wv    = (const float*)d_in[5];
    const float* wo    = (const float*)d_in[6];
    const float* wfreq = (const float*)d_in[7];
    const float* wph   = (const float*)d_in[8];
    const float* rtw   = (const float*)d_in[9];
    const float* rtb   = (const float*)d_in[10];
    const float* ew1   = (const float*)d_in[11];
    const float* eb1   = (const float*)d_in[12];
    const float* ew2   = (const float*)d_in[13];
    const float* eb2   = (const float*)d_in[14];
    const float* ln_g  = (const float*)d_in[15];
    const float* ln_b  = (const float*)d_in[16];
    const float* pw    = (const float*)d_in[17];
    const float* pb    = (const float*)d_in[18];
    const float* uw    = (const float*)d_in[19];
    const float* ub    = (const float*)d_in[20];
    float* out = (float*)d_out;

    float *ph, *pq, *pk, *pv, *pao;
    cudaGetSymbolAddress((void**)&ph,  g_h);
    cudaGetSymbolAddress((void**)&pq,  g_q);
    cudaGetSymbolAddress((void**)&pk,  g_k);
    cudaGetSymbolAddress((void**)&pv,  g_v);
    cudaGetSymbolAddress((void**)&pao, g_ao);

    cudaFuncSetAttribute(attn_kernel, cudaFuncAttributeMaxDynamicSharedMemorySize, ATTN_SMEM);
    cudaFuncSetAttribute(ffn_kernel,  cudaFuncAttributeMaxDynamicSharedMemorySize, FFN_SMEM);

    embed_kernel<<<T_, D_>>>(x, emb_w, emb_b);

    dim3 gg(D_/64, T_/128);
    for (int i = 0; i < NL_; i++) {
        const float* Wq = wq + (size_t)i*D_*D_;
        const float* Wk = wk + (size_t)i*D_*D_;
        const float* Wv = wv + (size_t)i*D_*D_;
        const float* Wo = wo + (size_t)i*D_*D_;
        sgemm128<<<gg, 256>>>(ph, Wq, nullptr, pq);
        sgemm128<<<gg, 256>>>(ph, Wk, nullptr, pk);
        sgemm128<<<gg, 256>>>(ph, Wv, nullptr, pv);
        attn_kernel<<<B_*H_, L_, ATTN_SMEM>>>(pq, pk, pv, wfreq, wph, pao, i);
        sgemm128<<<gg, 256>>>(pao, Wo, ph, ph);   // out proj + residual

        if (i % 2 == 0) {
            int m = i / 2;
            reset_kernel<<<1, 32>>>();
            router_kernel<<<T_/8, 256>>>(rtw + (size_t)m*D_*NE_, rtb + m*NE_);
            ffn_kernel<<<dim3(512, NE_), 256, FFN_SMEM>>>(
                ew1 + (size_t)m*NE_*D_*DFF_, eb1 + (size_t)m*NE_*DFF_,
                ew2 + (size_t)m*NE_*DFF_*D_, eb2 + (size_t)m*NE_*D_);
            combine_kernel<<<T_, D_>>>();
        }
    }
    head_kernel<<<B_, D_>>>(ln_g, ln_b, pw, pb, uw, ub, out);
}

// round 4
// speedup vs baseline: 2.6980x; 2.6980x over previous
#include <cuda_runtime.h>
#include <math.h>
#include <stdint.h>

#define B_ 128
#define L_ 128
#define T_ (B_*L_)
#define DIN_ 6
#define D_ 256
#define H_ 8
#define DK_ 32
#define NL_ 6
#define NE_ 8
#define DFF_ 1024
#define NOUT_ 5

#define ATTN_SMEM ((128*33 + 128*129 + 128)*4)

// ---------------- device scratch (no allocations allowed) ----------------
__device__ float g_h[T_*D_];
__device__ float g_q[T_*D_];
__device__ float g_k[T_*D_];
__device__ float g_v[T_*D_];
__device__ float g_ao[T_*D_];
__device__ float g_eo[(size_t)NE_*T_*D_];     // per-expert FFN outputs by list position
__device__ float g_hb[(size_t)NE_*T_*DFF_];   // FFN hidden (gelu output), per (e, pos)
__device__ int   g_cnt[NE_];
__device__ int   g_list[NE_*T_];
__device__ int   g_ebuf[T_*2];
__device__ int   g_pbuf[T_*2];
__device__ float g_wbuf[T_*2];

// ---------------- embed: h = x @ emb_w + emb_b ----------------
__global__ void embed_kernel(const float* __restrict__ x,
                             const float* __restrict__ w,
                             const float* __restrict__ b) {
    int t = blockIdx.x, d = threadIdx.x;
    float acc = b[d];
#pragma unroll
    for (int i = 0; i < DIN_; i++) acc += x[t*DIN_ + i] * w[i*D_ + d];
    g_h[(size_t)t*D_ + d] = acc;
}

// ---------------- TF32 tensor-core GEMM ----------------
// C[M,N] = A[M,K] @ W[K,N]  (both row-major), fused epilogues.
// Block tile 128x128, 8 warps (4M x 2N), warp tile 32x64 (2 m16 x 8 n8), K-chunk 32.
#define EPI_NONE      0
#define EPI_RES       1
#define EPI_BIAS_GELU 2
#define EPI_BIAS      3

__device__ __forceinline__ uint32_t f2tf(float x) {
    uint32_t u;
    asm("cvt.rna.tf32.f32 %0, %1;" : "=r"(u) : "f"(x));
    return u;
}

#define LDA_S 36
#define LDB_S 136

template<int EPI>
__global__ __launch_bounds__(256)
void mma_gemm(const float* __restrict__ A, int lda, size_t strideA,
              const float* __restrict__ W, int ldw, size_t strideW,
              float* __restrict__ C, int ldc, size_t strideC,
              const float* __restrict__ bias, size_t strideBias,
              const float* __restrict__ res,
              const int* __restrict__ gather, size_t strideGather,
              const int* __restrict__ cntPtr,
              int M, int N, int K) {
    __shared__ float As[128*LDA_S];
    __shared__ float Bs[32*LDB_S];

    int e = blockIdx.z;
    const float* Ae = A + (size_t)e*strideA;
    const float* We = W + (size_t)e*strideW;
    float*       Ce = C + (size_t)e*strideC;
    const float* be = bias ? bias + (size_t)e*strideBias : nullptr;
    const int*   ge = gather ? gather + (size_t)e*strideGather : nullptr;
    int Mloc = cntPtr ? cntPtr[e] : M;

    int bm = blockIdx.x * 128;
    if (bm >= Mloc) return;
    int bn = blockIdx.y * 128;

    int tid = threadIdx.x;
    int lane = tid & 31;
    int wid = tid >> 5;
    int wm = wid & 3;        // 0..3  M direction
    int wn = wid >> 2;       // 0..1  N direction

    float acc[2][8][4];
#pragma unroll
    for (int mt = 0; mt < 2; mt++)
#pragma unroll
        for (int nt = 0; nt < 8; nt++)
#pragma unroll
            for (int i = 0; i < 4; i++) acc[mt][nt][i] = 0.f;

    for (int k0 = 0; k0 < K; k0 += 32) {
        // ---- load A tile 128x32 (gathered, guarded) ----
#pragma unroll
        for (int p = 0; p < 4; p++) {
            int f = tid + p*256;
            int r = f >> 3;              // 0..127
            int c4 = (f & 7) << 2;       // 0,4,...,28
            float4 v = make_float4(0.f, 0.f, 0.f, 0.f);
            int grow = bm + r;
            if (grow < Mloc) {
                int arow = ge ? ge[grow] : grow;
                v = *(const float4*)(Ae + (size_t)arow*lda + k0 + c4);
            }
            float* dst = As + r*LDA_S + c4;
            dst[0] = __uint_as_float(f2tf(v.x));
            dst[1] = __uint_as_float(f2tf(v.y));
            dst[2] = __uint_as_float(f2tf(v.z));
            dst[3] = __uint_as_float(f2tf(v.w));
        }
        // ---- load B tile 32x128 ----
#pragma unroll
        for (int p = 0; p < 4; p++) {
            int f = tid + p*256;
            int kr = f >> 5;             // 0..31
            int c4 = (f & 31) << 2;      // 0..124
            float4 v = *(const float4*)(We + (size_t)(k0 + kr)*ldw + bn + c4);
            float* dst = Bs + kr*LDB_S + c4;
            dst[0] = __uint_as_float(f2tf(v.x));
            dst[1] = __uint_as_float(f2tf(v.y));
            dst[2] = __uint_as_float(f2tf(v.z));
            dst[3] = __uint_as_float(f2tf(v.w));
        }
        __syncthreads();

        const float* ar0 = As + (wm*32 + (lane >> 2))*LDA_S + (lane & 3);
        const float* br0 = Bs + (lane & 3)*LDB_S + wn*64 + (lane >> 2);
#pragma unroll
        for (int kk = 0; kk < 32; kk += 8) {
            uint32_t af[2][4];
#pragma unroll
            for (int mt = 0; mt < 2; mt++) {
                const float* ar = ar0 + mt*16*LDA_S + kk;
                af[mt][0] = __float_as_uint(ar[0]);
                af[mt][1] = __float_as_uint(ar[8*LDA_S]);
                af[mt][2] = __float_as_uint(ar[4]);
                af[mt][3] = __float_as_uint(ar[8*LDA_S + 4]);
            }
            uint32_t bf[8][2];
#pragma unroll
            for (int nt = 0; nt < 8; nt++) {
                const float* br = br0 + kk*LDB_S + nt*8;
                bf[nt][0] = __float_as_uint(br[0]);
                bf[nt][1] = __float_as_uint(br[4*LDB_S]);
            }
#pragma unroll
            for (int mt = 0; mt < 2; mt++)
#pragma unroll
                for (int nt = 0; nt < 8; nt++) {
                    asm volatile(
                        "mma.sync.aligned.m16n8k8.row.col.f32.tf32.tf32.f32 "
                        "{%0,%1,%2,%3}, {%4,%5,%6,%7}, {%8,%9}, {%0,%1,%2,%3};"
                        : "+f"(acc[mt][nt][0]), "+f"(acc[mt][nt][1]),
                          "+f"(acc[mt][nt][2]), "+f"(acc[mt][nt][3])
                        : "r"(af[mt][0]), "r"(af[mt][1]), "r"(af[mt][2]), "r"(af[mt][3]),
                          "r"(bf[nt][0]), "r"(bf[nt][1]));
                }
        }
        __syncthreads();
    }

    // ---- epilogue ----
#pragma unroll
    for (int mt = 0; mt < 2; mt++) {
#pragma unroll
        for (int nt = 0; nt < 8; nt++) {
            int r0 = bm + wm*32 + mt*16 + (lane >> 2);
            int c0 = bn + wn*64 + nt*8 + ((lane & 3) << 1);
#pragma unroll
            for (int i = 0; i < 4; i++) {
                int row = r0 + ((i >> 1) << 3);
                int col = c0 + (i & 1);
                if (row < Mloc) {
                    float v = acc[mt][nt][i];
                    if (EPI == EPI_BIAS_GELU) {
                        v += be[col];
                        v = 0.5f*v*(1.f + erff(v*0.7071067811865475f));
                    } else if (EPI == EPI_BIAS) {
                        v += be[col];
                    } else if (EPI == EPI_RES) {
                        v += res[(size_t)row*ldc + col];
                    }
                    Ce[(size_t)row*ldc + col] = v;
                }
            }
        }
    }
}

// ---------------- wave attention: one block per (b, head) ----------------
__global__ void attn_kernel(const float* __restrict__ q, const float* __restrict__ k,
                            const float* __restrict__ v, const float* __restrict__ wfreq,
                            const float* __restrict__ wphase, float* __restrict__ out,
                            int layer) {
    extern __shared__ float sm[];
    float* kv  = sm;                         // 128*33 (K tile, later reused as V tile)
    float* ps  = sm + 128*33;                // 128*129 score rows (padded)
    float* wav = sm + 128*33 + 128*129;      // 128 wave values

    int b = blockIdx.x >> 3, hh = blockIdx.x & 7;
    int t = threadIdx.x;
    float freq  = wfreq[layer*H_ + hh];
    float phase = wphase[layer*H_ + hh];
    wav[t] = cosf(6.283185307179586f * freq * (float)t + phase);

    const float* qb = q + (size_t)(b*L_)*D_ + hh*DK_;
    const float* kb = k + (size_t)(b*L_)*D_ + hh*DK_;
    const float* vb = v + (size_t)(b*L_)*D_ + hh*DK_;

    for (int i = t; i < L_*DK_; i += L_) {
        int r = i >> 5, c = i & 31;
        kv[r*33 + c] = kb[(size_t)r*D_ + c];
    }
    float qr[DK_];
#pragma unroll
    for (int d = 0; d < DK_; d++) qr[d] = qb[(size_t)t*D_ + d];
    __syncthreads();

    const float scale = 0.17677669529663688f;   // 32^-0.5
    float mx = -1e30f;
    for (int j = 0; j < L_; j++) {
        float s = 0.f;
#pragma unroll
        for (int d = 0; d < DK_; d++) s += qr[d]*kv[j*33 + d];
        s = s * scale * wav[j];
        ps[t*129 + j] = s;
        mx = fmaxf(mx, s);
    }
    float sum = 0.f;
    for (int j = 0; j < L_; j++) {
        float e = expf(ps[t*129 + j] - mx);
        ps[t*129 + j] = e;
        sum += e;
    }
    float inv = 1.f / sum;
    __syncthreads();   // everyone done with K tile
    for (int i = t; i < L_*DK_; i += L_) {
        int r = i >> 5, c = i & 31;
        kv[r*33 + c] = vb[(size_t)r*D_ + c];
    }
    __syncthreads();

    float o[DK_];
#pragma unroll
    for (int d = 0; d < DK_; d++) o[d] = 0.f;
    for (int j = 0; j < L_; j++) {
        float p = ps[t*129 + j];
#pragma unroll
        for (int d = 0; d < DK_; d++) o[d] += p*kv[j*33 + d];
    }
    float* ob = out + (size_t)(b*L_ + t)*D_ + hh*DK_;
#pragma unroll
    for (int d = 0; d < DK_; d++) ob[d] = o[d]*inv;
}

// ---------------- MoE router + bucketing (one warp per token) ----------------
__global__ void reset_kernel() {
    if (threadIdx.x < NE_) g_cnt[threadIdx.x] = 0;
}

__global__ void router_kernel(const float* __restrict__ rtw, const float* __restrict__ rtb) {
    int lane = threadIdx.x & 31;
    int t = blockIdx.x*8 + (threadIdx.x >> 5);
    const float* xr = g_h + (size_t)t*D_;
    float acc[NE_];
#pragma unroll
    for (int e = 0; e < NE_; e++) acc[e] = 0.f;
    for (int d = lane; d < D_; d += 32) {
        float xv = xr[d];
#pragma unroll
        for (int e = 0; e < NE_; e++) acc[e] += xv * rtw[d*NE_ + e];
    }
#pragma unroll
    for (int off = 16; off > 0; off >>= 1)
#pragma unroll
        for (int e = 0; e < NE_; e++) acc[e] += __shfl_down_sync(0xffffffffu, acc[e], off);
    if (lane == 0) {
        float l0 = -1e30f, l1 = -1e30f; int e0 = 0, e1 = 0;
#pragma unroll
        for (int e = 0; e < NE_; e++) {
            float vv = acc[e] + rtb[e];
            if (vv > l0) { l1 = l0; e1 = e0; l0 = vv; e0 = e; }
            else if (vv > l1) { l1 = vv; e1 = e; }
        }
        float ew = expf(l1 - l0);          // normalized top-2 softmax weights
        float w0 = 1.f/(1.f + ew);
        float w1 = ew/(1.f + ew);
        int p0 = atomicAdd(&g_cnt[e0], 1); g_list[e0*T_ + p0] = t;
        int p1 = atomicAdd(&g_cnt[e1], 1); g_list[e1*T_ + p1] = t;
        g_ebuf[2*t]   = e0; g_pbuf[2*t]   = p0; g_wbuf[2*t]   = w0;
        g_ebuf[2*t+1] = e1; g_pbuf[2*t+1] = p1; g_wbuf[2*t+1] = w1;
    }
}

// ---------------- combine: h += w0*eo[e0,p0] + w1*eo[e1,p1] ----------------
__global__ void combine_kernel() {
    int t = blockIdx.x, d = threadIdx.x;
    float v = g_h[(size_t)t*D_ + d];
#pragma unroll
    for (int kk = 0; kk < 2; kk++) {
        int e = g_ebuf[2*t + kk];
        int p = g_pbuf[2*t + kk];
        float w = g_wbuf[2*t + kk];
        v += w * g_eo[((size_t)e*T_ + p)*D_ + d];
    }
    g_h[(size_t)t*D_ + d] = v;
}

// ---------------- head: LN(last token) -> pred / softplus(unc) ----------------
__global__ void head_kernel(const float* __restrict__ ln_g, const float* __restrict__ ln_b,
                            const float* __restrict__ pw, const float* __restrict__ pb,
                            const float* __restrict__ uw, const float* __restrict__ ub,
                            float* __restrict__ out) {
    __shared__ float red[256];
    __shared__ float norm[256];
    int b = blockIdx.x, d = threadIdx.x;
    float hv = g_h[(size_t)(b*L_ + L_ - 1)*D_ + d];
    red[d] = hv; __syncthreads();
    for (int s = 128; s > 0; s >>= 1) { if (d < s) red[d] += red[d+s]; __syncthreads(); }
    float mu = red[0] * (1.f/256.f);
    __syncthreads();
    float df = hv - mu;
    red[d] = df*df; __syncthreads();
    for (int s = 128; s > 0; s >>= 1) { if (d < s) red[d] += red[d+s]; __syncthreads(); }
    float var = red[0] * (1.f/256.f);
    norm[d] = df * rsqrtf(var + 1e-5f) * ln_g[d] + ln_b[d];
    __syncthreads();
    if (d < 2*NOUT_) {
        int o = d % NOUT_;
        bool un = (d >= NOUT_);
        const float* W = un ? uw : pw;
        float acc = un ? ub[o] : pb[o];
        for (int i = 0; i < D_; i++) acc += norm[i]*W[i*NOUT_ + o];
        if (!un) out[b*NOUT_ + o] = acc;
        else     out[B_*NOUT_ + b*NOUT_ + o] = (acc > 20.f) ? acc : log1pf(expf(acc));
    }
}

// ---------------- launch ----------------
extern "C" void kernel_launch(void* const* d_in, const int* in_sizes, int n_in,
                              void* d_out, int out_size) {
    const float* x     = (const float*)d_in[0];
    const float* emb_w = (const float*)d_in[1];
    const float* emb_b = (const float*)d_in[2];
    const float* wq    = (const float*)d_in[3];
    const float* wk    = (const float*)d_in[4];
    const float* wv    = (const float*)d_in[5];
    const float* wo    = (const float*)d_in[6];
    const float* wfreq = (const float*)d_in[7];
    const float* wph   = (const float*)d_in[8];
    const float* rtw   = (const float*)d_in[9];
    const float* rtb   = (const float*)d_in[10];
    const float* ew1   = (const float*)d_in[11];
    const float* eb1   = (const float*)d_in[12];
    const float* ew2   = (const float*)d_in[13];
    const float* eb2   = (const float*)d_in[14];
    const float* ln_g  = (const float*)d_in[15];
    const float* ln_b  = (const float*)d_in[16];
    const float* pw    = (const float*)d_in[17];
    const float* pb    = (const float*)d_in[18];
    const float* uw    = (const float*)d_in[19];
    const float* ub    = (const float*)d_in[20];
    float* out = (float*)d_out;

    float *ph, *pq, *pk, *pv, *pao, *peo, *phb;
    int *pcnt, *plist;
    cudaGetSymbolAddress((void**)&ph,   g_h);
    cudaGetSymbolAddress((void**)&pq,   g_q);
    cudaGetSymbolAddress((void**)&pk,   g_k);
    cudaGetSymbolAddress((void**)&pv,   g_v);
    cudaGetSymbolAddress((void**)&pao,  g_ao);
    cudaGetSymbolAddress((void**)&peo,  g_eo);
    cudaGetSymbolAddress((void**)&phb,  g_hb);
    cudaGetSymbolAddress((void**)&pcnt, g_cnt);
    cudaGetSymbolAddress((void**)&plist,g_list);

    cudaFuncSetAttribute(attn_kernel, cudaFuncAttributeMaxDynamicSharedMemorySize, ATTN_SMEM);

    embed_kernel<<<T_, D_>>>(x, emb_w, emb_b);

    dim3 gproj(T_/128, D_/128, 1);        // (128, 2)
    for (int i = 0; i < NL_; i++) {
        const float* Wq = wq + (size_t)i*D_*D_;
        const float* Wk = wk + (size_t)i*D_*D_;
        const float* Wv = wv + (size_t)i*D_*D_;
        const float* Wo = wo + (size_t)i*D_*D_;

        mma_gemm<EPI_NONE><<<gproj, 256>>>(ph, D_, 0, Wq, D_, 0, pq, D_, 0,
                                           nullptr, 0, nullptr, nullptr, 0, nullptr,
                                           T_, D_, D_);
        mma_gemm<EPI_NONE><<<gproj, 256>>>(ph, D_, 0, Wk, D_, 0, pk, D_, 0,
                                           nullptr, 0, nullptr, nullptr, 0, nullptr,
                                           T_, D_, D_);
        mma_gemm<EPI_NONE><<<gproj, 256>>>(ph, D_, 0, Wv, D_, 0, pv, D_, 0,
                                           nullptr, 0, nullptr, nullptr, 0, nullptr,
                                           T_, D_, D_);
        attn_kernel<<<B_*H_, L_, ATTN_SMEM>>>(pq, pk, pv, wfreq, wph, pao, i);
        mma_gemm<EPI_RES><<<gproj, 256>>>(pao, D_, 0, Wo, D_, 0, ph, D_, 0,
                                          nullptr, 0, ph, nullptr, 0, nullptr,
                                          T_, D_, D_);   // out proj + residual

        if (i % 2 == 0) {
            int m = i / 2;
            reset_kernel<<<1, 32>>>();
            router_kernel<<<T_/8, 256>>>(rtw + (size_t)m*D_*NE_, rtb + m*NE_);

            // FFN1: per expert, gathered rows of g_h: hb = gelu(x @ w1 + b1)
            dim3 g1(T_/128, DFF_/128, NE_);   // (128, 8, 8)
            mma_gemm<EPI_BIAS_GELU><<<g1, 256>>>(
                ph, D_, 0,
                ew1 + (size_t)m*NE_*D_*DFF_, DFF_, (size_t)D_*DFF_,
                phb, DFF_, (size_t)T_*DFF_,
                eb1 + (size_t)m*NE_*DFF_, DFF_,
                nullptr,
                plist, T_, pcnt,
                T_, DFF_, D_);

            // FFN2: eo = hb @ w2 + b2
            dim3 g2(T_/128, D_/128, NE_);     // (128, 2, 8)
            mma_gemm<EPI_BIAS><<<g2, 256>>>(
                phb, DFF_, (size_t)T_*DFF_,
                ew2 + (size_t)m*NE_*DFF_*D_, D_, (size_t)DFF_*D_,
                peo, D_, (size_t)T_*D_,
                eb2 + (size_t)m*NE_*D_, D_,
                nullptr,
                nullptr, 0, pcnt,
                T_, D_, DFF_);

            combine_kernel<<<T_, D_>>>();
        }
    }
    head_kernel<<<B_, D_>>>(ln_g, ln_b, pw, pb, uw, ub, out);
}